// round 8
// baseline (speedup 1.0000x reference)
#include <cuda_runtime.h>
#include <cuda_bf16.h>
#include <cstdint>
#include <cstddef>

// Problem constants
#define BSZ 4096
#define TSZ 100
#define FSZ 13
#define HSZ 100
#define G4  400

// GEMM (k_gemm_mma) constants
#define KP   112
#define LDA  120
#define LDB  120

// Recurrent tensor kernel constants
#define RW    13
#define RTH   (RW*32)
#define W2N   23296         // words per split
#define HROW  68            // h row stride in words (conflict-free ldmatrix)

// ---------------------------------------------------------------------------
// Scratch (device globals)
// ---------------------------------------------------------------------------
__device__ __nv_bfloat16 g_h0hi[(size_t)BSZ * TSZ * HSZ];
__device__ __nv_bfloat16 g_h0lo[(size_t)BSZ * TSZ * HSZ];
__device__ __nv_bfloat16 g_bhi[G4 * KP];
__device__ __nv_bfloat16 g_blo[G4 * KP];
__device__ float g_zpack [(size_t)BSZ * TSZ * G4];
__device__ float g_z0pack[(size_t)BSZ * TSZ * G4];
__device__ int   g_off_arr[BSZ + 1];
__device__ uint32_t g_w2hi0[W2N], g_w2lo0[W2N];
__device__ uint32_t g_w2hi1[W2N], g_w2lo1[W2N];

// ---------------------------------------------------------------------------
// Helpers
// ---------------------------------------------------------------------------
__device__ __forceinline__ float tanha(float x) {             // MUFU.TANH
    float y;
    asm("tanh.approx.f32 %0, %1;" : "=f"(y) : "f"(x));
    return y;
}
__device__ __forceinline__ float siga(float x) {              // approx sigmoid
    return fmaf(0.5f, tanha(0.5f * x), 0.5f);
}
__device__ __forceinline__ void ffma2(unsigned long long &d,
                                      unsigned long long a,
                                      unsigned long long b) {
    asm("fma.rn.f32x2 %0, %1, %2, %0;" : "+l"(d) : "l"(a), "l"(b));
}
__device__ __forceinline__ unsigned long long pk(float lo, float hi) {
    unsigned long long r;
    asm("mov.b64 %0, {%1, %2};" : "=l"(r) : "f"(lo), "f"(hi));
    return r;
}
__device__ __forceinline__ float psum(unsigned long long a) {
    float lo = __uint_as_float((unsigned)(a & 0xffffffffull));
    float hi = __uint_as_float((unsigned)(a >> 32));
    return lo + hi;
}
__device__ __forceinline__ void mma_bf16(float* d, const uint32_t* a,
                                         uint32_t b0, uint32_t b1) {
    asm volatile(
        "mma.sync.aligned.m16n8k16.row.col.f32.bf16.bf16.f32 "
        "{%0,%1,%2,%3}, {%4,%5,%6,%7}, {%8,%9}, {%0,%1,%2,%3};"
        : "+f"(d[0]), "+f"(d[1]), "+f"(d[2]), "+f"(d[3])
        : "r"(a[0]), "r"(a[1]), "r"(a[2]), "r"(a[3]), "r"(b0), "r"(b1));
}
__device__ __forceinline__ void ldsm4(uint32_t* r, uint32_t addr) {
    asm volatile("ldmatrix.sync.aligned.m8n8.x4.shared.b16 {%0,%1,%2,%3}, [%4];"
        : "=r"(r[0]), "=r"(r[1]), "=r"(r[2]), "=r"(r[3]) : "r"(addr));
}
__device__ __forceinline__ uint32_t smem_u32(const void* p) {
    uint32_t a;
    asm("{ .reg .u64 t; cvta.to.shared.u64 t, %1; cvt.u32.u64 %0, t; }"
        : "=r"(a) : "l"(p));
    return a;
}
__device__ __forceinline__ uint32_t pack_bf16x2(float a, float b) {
    __nv_bfloat16 x = __float2bfloat16(a), y = __float2bfloat16(b);
    return (uint32_t)__bfloat16_as_ushort(x)
         | ((uint32_t)__bfloat16_as_ushort(y) << 16);
}

// ===========================================================================
// Kernel S: exclusive prefix scan of lengths (1 CTA)
// ===========================================================================
__global__ void __launch_bounds__(512, 1) k_scan(const int* __restrict__ lengths)
{
    __shared__ int s[512];
    const int tid = threadIdx.x;
    const int base = tid * 8;
    int v[8]; int loc = 0;
    #pragma unroll
    for (int i = 0; i < 8; i++) { v[i] = lengths[base + i]; loc += v[i]; }
    s[tid] = loc;
    __syncthreads();
    for (int d = 1; d < 512; d <<= 1) {
        int t = (tid >= d) ? s[tid - d] : 0;
        __syncthreads();
        s[tid] += t;
        __syncthreads();
    }
    int run = s[tid] - loc;
    #pragma unroll
    for (int i = 0; i < 8; i++) { g_off_arr[base + i] = run; run += v[i]; }
    if (tid == 511) g_off_arr[BSZ] = s[511];
}

// ===========================================================================
// Kernel W1: split W_ih1 into bf16 hi/lo (gemm layout)
// ===========================================================================
__global__ void __launch_bounds__(256, 1) k_wsplit(const float* __restrict__ Wih1)
{
    int idx = blockIdx.x * 256 + threadIdx.x;
    if (idx < G4 * KP) {
        int n = idx / KP, k = idx % KP;
        float v = (k < HSZ) ? Wih1[n * HSZ + k] : 0.f;
        __nv_bfloat16 hi = __float2bfloat16(v);
        g_bhi[idx] = hi;
        g_blo[idx] = __float2bfloat16(v - __bfloat162float(hi));
    }
}

// ===========================================================================
// Kernel W2: Whh in pair-packed fragment layout (LDS.64-friendly)
// ===========================================================================
__global__ void __launch_bounds__(256, 1)
k_wprep(const float* __restrict__ W, uint32_t* __restrict__ dhi,
        uint32_t* __restrict__ dlo)
{
    int j = blockIdx.x * 256 + threadIdx.x;
    if (j >= W2N) return;
    int sel = j & 1;
    int pp  = (j >> 1) & 31;
    int tg  = pp >> 3, g = pp & 7;
    int grp = j >> 6;
    int kt  = grp % 7, n = grp / 7;
    int row = n * 8 + g;
    int gate = row / 104, u = row % 104;
    int k    = kt * 16 + 2 * tg + 8 * sel;
    float f0 = (u < HSZ && k     < HSZ) ? W[(gate * HSZ + u) * HSZ + k]     : 0.f;
    float f1 = (u < HSZ && k + 1 < HSZ) ? W[(gate * HSZ + u) * HSZ + k + 1] : 0.f;
    __nv_bfloat16 h0 = __float2bfloat16(f0), h1 = __float2bfloat16(f1);
    float r0 = f0 - __bfloat162float(h0), r1 = f1 - __bfloat162float(h1);
    dhi[j] = (uint32_t)__bfloat16_as_ushort(h0)
           | ((uint32_t)__bfloat16_as_ushort(h1) << 16);
    dlo[j] = pack_bf16x2(r0, r1);
}

// ===========================================================================
// Kernel Z0: g_z0pack = bias0 + x @ Wih0^T (packed rows)
// ===========================================================================
__global__ void __launch_bounds__(512, 1)
k_zx0(const float* __restrict__ x, const int* __restrict__ lengths,
      const float* __restrict__ Wih0,
      const float* __restrict__ bih0, const float* __restrict__ bhh0)
{
    __shared__ float sX[1400];
    __shared__ int sLen[32], sOff[32];
    const int tid = threadIdx.x;
    const int grow0 = blockIdx.x * 32;
    if (tid < 32) {
        sLen[tid] = lengths[grow0 + tid];
        sOff[tid] = g_off_arr[grow0 + tid];
    }
    const int u = tid;
    const bool act = (u < G4);
    unsigned long long wp[7];
    float b = 0.f;
    if (act) {
        float wr[14];
        #pragma unroll
        for (int k = 0; k < FSZ; k++) wr[k] = Wih0[u * FSZ + k];
        wr[13] = 0.f;
        #pragma unroll
        for (int i = 0; i < 7; i++) wp[i] = pk(wr[2*i], wr[2*i+1]);
        b = bih0[u] + bhh0[u];
    }
    __syncthreads();

    for (int r = 0; r < 32; r++) {
        const int len = sLen[r], off = sOff[r];
        __syncthreads();
        const float* xs = x + (size_t)(grow0 + r) * (TSZ * FSZ);
        for (int i = tid; i < 1400; i += 512) {
            int t = i / 14, k = i % 14;
            sX[i] = (k < FSZ) ? xs[t * FSZ + k] : 0.f;
        }
        __syncthreads();
        if (act) {
            for (int t = 0; t < len; t++) {
                unsigned long long acc = pk(b, 0.f);
                #pragma unroll
                for (int kp = 0; kp < 7; kp++)
                    ffma2(acc, wp[kp], *(const unsigned long long*)&sX[t*14 + 2*kp]);
                g_z0pack[(size_t)(off + t) * G4 + u] = psum(acc);
            }
        }
    }
}

// ===========================================================================
// Kernel R: two-group pipelined tensor-core LSTM layer
//   rows 0-15 = group A, rows 16-31 = group B (independent sequences)
//   phase1: MMA_A(t) overlaps act_B(t-1); phase2: MMA_B(t) overlaps act_A(t)
// ===========================================================================
template<int MODE>
__global__ void __launch_bounds__(RTH, 1)
k_rec(const int* __restrict__ lengths,
      const float* __restrict__ Wfc, const float* __restrict__ bfc,
      float* __restrict__ out)
{
    extern __shared__ char smc[];
    uint32_t* sWhi = (uint32_t*)(smc);                   // 93184 B
    uint32_t* sWlo = (uint32_t*)(smc + 93184);           // 93184 B
    uint32_t* sHhi = (uint32_t*)(smc + 186368);          // 8704 B (single buf)
    uint32_t* sHlo = (uint32_t*)(smc + 195072);          // 8704 B
    int*   sLen = (int*)(smc + 203776);
    int*   sOff = (int*)(smc + 203904);
    float* sWf  = (float*)(smc + 204032);
    float* sHF  = (float*)(smc);                         // fc reuse (after loop)

    const uint32_t* gwhi = MODE ? g_w2hi1 : g_w2hi0;
    const uint32_t* gwlo = MODE ? g_w2lo1 : g_w2lo0;
    const float*    zsrc = MODE ? g_zpack : g_z0pack;

    const int tid = threadIdx.x;
    const int grow0 = blockIdx.x * 32;

    for (int i = tid; i < W2N; i += RTH) { sWhi[i] = gwhi[i]; sWlo[i] = gwlo[i]; }
    for (int i = tid; i < 32 * HROW; i += RTH) { sHhi[i] = 0u; sHlo[i] = 0u; }
    if (tid < 32) {
        sLen[tid] = lengths[grow0 + tid];
        sOff[tid] = g_off_arr[grow0 + tid];
    }
    if (MODE == 1 && tid < HSZ) sWf[tid] = Wfc[tid];
    __syncthreads();

    int Lmax = 0;
    #pragma unroll
    for (int r = 0; r < 32; r++) Lmax = max(Lmax, sLen[r]);

    const int w = tid >> 5, lane = tid & 31;
    const int g = lane >> 2, tg = lane & 3;
    const int u0 = w * 8 + 2 * tg;
    const bool cv = (u0 < HSZ);

    const uint32_t sb = smem_u32(smc);
    const uint32_t lmoff = ((lane & 15) * HROW + (lane >> 4) * 4) * 4;
    const uint32_t hHiA = sb + 186368 + lmoff;                 // rows 0-15
    const uint32_t hLoA = sb + 195072 + lmoff;
    const uint32_t hHiB = hHiA + 16 * HROW * 4;                // rows 16-31
    const uint32_t hLoB = hLoA + 16 * HROW * 4;

    // ri 0,1 -> group A rows g, 8+g ; ri 2,3 -> group B rows 16+g, 24+g
    int rown[4], lenr[4], offr[4];
    #pragma unroll
    for (int ri = 0; ri < 4; ri++) {
        rown[ri] = (ri >> 1) * 16 + (ri & 1) * 8 + g;
        lenr[ri] = sLen[rown[ri]];
        offr[ri] = sOff[rown[ri]];
    }
    float c[4][2] = {{0.f,0.f},{0.f,0.f},{0.f,0.f},{0.f,0.f}};
    float h[4][2] = {{0.f,0.f},{0.f,0.f},{0.f,0.f},{0.f,0.f}};

    float DA[4][4], DB[4][4];
    float2 zA[2][4], zB[2][4];

    // prefetch z_B(0)
    #pragma unroll
    for (int r2 = 0; r2 < 2; r2++) {
        const bool lv = cv && (0 < lenr[2 + r2]);
        const size_t zb = (size_t)offr[2 + r2] * G4;
        #pragma unroll
        for (int G = 0; G < 4; G++)
            zB[r2][G] = lv ? *(const float2*)&zsrc[zb + G * HSZ + u0]
                           : make_float2(0.f, 0.f);
    }

    #pragma unroll 1
    for (int t = 0; t < Lmax; t++) {
        // ---- phase 1: MMA_A(t) || act_B(t-1) ----
        // prefetch z_A(t) (consumed in phase 2)
        #pragma unroll
        for (int r2 = 0; r2 < 2; r2++) {
            const bool lv = cv && (t < lenr[r2]);
            const size_t zb = (size_t)(offr[r2] + t) * G4;
            #pragma unroll
            for (int G = 0; G < 4; G++)
                zA[r2][G] = lv ? *(const float2*)&zsrc[zb + G * HSZ + u0]
                               : make_float2(0.f, 0.f);
        }
        #pragma unroll
        for (int G = 0; G < 4; G++)
            #pragma unroll
            for (int q = 0; q < 4; q++) DA[G][q] = 0.f;
        #pragma unroll
        for (int kt = 0; kt < 7; kt++) {
            uint32_t ahi[4], alo[4];
            ldsm4(ahi, hHiA + kt * 32);
            ldsm4(alo, hLoA + kt * 32);
            #pragma unroll
            for (int G = 0; G < 4; G++) {
                const int b2 = (((G * 13 + w) * 7 + kt) * 32 + tg * 8 + g) * 2;
                uint2 bh = *(const uint2*)&sWhi[b2];
                uint2 bl = *(const uint2*)&sWlo[b2];
                mma_bf16(DA[G], ahi, bh.x, bh.y);
                mma_bf16(DA[G], alo, bh.x, bh.y);
                mma_bf16(DA[G], ahi, bl.x, bl.y);
            }
        }
        if (t > 0) {
            // act_B(t-1): D_B from previous phase 2, z_B(t-1) in zB
            const int tb = t - 1;
            #pragma unroll
            for (int r2 = 0; r2 < 2; r2++) {
                const int ri = 2 + r2;
                const bool upd = cv && (tb < lenr[ri]);
                #pragma unroll
                for (int j = 0; j < 2; j++) {
                    float zi = DB[0][r2 * 2 + j] + (j ? zB[r2][0].y : zB[r2][0].x);
                    float zf = DB[1][r2 * 2 + j] + (j ? zB[r2][1].y : zB[r2][1].x);
                    float zg = DB[2][r2 * 2 + j] + (j ? zB[r2][2].y : zB[r2][2].x);
                    float zo = DB[3][r2 * 2 + j] + (j ? zB[r2][3].y : zB[r2][3].x);
                    float cn = siga(zf) * c[ri][j] + siga(zi) * tanha(zg);
                    float hn = siga(zo) * tanha(cn);
                    if (upd) { c[ri][j] = cn; h[ri][j] = hn; }
                }
                __nv_bfloat16 b0 = __float2bfloat16(h[ri][0]);
                __nv_bfloat16 b1 = __float2bfloat16(h[ri][1]);
                uint32_t hw = (uint32_t)__bfloat16_as_ushort(b0)
                            | ((uint32_t)__bfloat16_as_ushort(b1) << 16);
                uint32_t lw = pack_bf16x2(h[ri][0] - __bfloat162float(b0),
                                          h[ri][1] - __bfloat162float(b1));
                const int word = rown[ri] * HROW + w * 4 + tg;
                sHhi[word] = hw; sHlo[word] = lw;
                if (MODE == 0 && upd) {
                    size_t o = ((size_t)offr[ri] + tb) * HSZ + u0;
                    *(uint32_t*)&g_h0hi[o] = hw;
                    *(uint32_t*)&g_h0lo[o] = lw;
                }
            }
        }
        __syncthreads();

        // ---- phase 2: MMA_B(t) || act_A(t) ----
        // prefetch z_B(t) (consumed next iteration / final)
        #pragma unroll
        for (int r2 = 0; r2 < 2; r2++) {
            const bool lv = cv && (t < lenr[2 + r2]);
            const size_t zb = (size_t)(offr[2 + r2] + t) * G4;
            #pragma unroll
            for (int G = 0; G < 4; G++)
                zB[r2][G] = lv ? *(const float2*)&zsrc[zb + G * HSZ + u0]
                               : make_float2(0.f, 0.f);
        }
        #pragma unroll
        for (int G = 0; G < 4; G++)
            #pragma unroll
            for (int q = 0; q < 4; q++) DB[G][q] = 0.f;
        #pragma unroll
        for (int kt = 0; kt < 7; kt++) {
            uint32_t ahi[4], alo[4];
            ldsm4(ahi, hHiB + kt * 32);
            ldsm4(alo, hLoB + kt * 32);
            #pragma unroll
            for (int G = 0; G < 4; G++) {
                const int b2 = (((G * 13 + w) * 7 + kt) * 32 + tg * 8 + g) * 2;
                uint2 bh = *(const uint2*)&sWhi[b2];
                uint2 bl = *(const uint2*)&sWlo[b2];
                mma_bf16(DB[G], ahi, bh.x, bh.y);
                mma_bf16(DB[G], alo, bh.x, bh.y);
                mma_bf16(DB[G], ahi, bl.x, bl.y);
            }
        }
        {
            // act_A(t): D_A from phase 1, z_A(t) in zA
            #pragma unroll
            for (int r2 = 0; r2 < 2; r2++) {
                const int ri = r2;
                const bool upd = cv && (t < lenr[ri]);
                #pragma unroll
                for (int j = 0; j < 2; j++) {
                    float zi = DA[0][r2 * 2 + j] + (j ? zA[r2][0].y : zA[r2][0].x);
                    float zf = DA[1][r2 * 2 + j] + (j ? zA[r2][1].y : zA[r2][1].x);
                    float zg = DA[2][r2 * 2 + j] + (j ? zA[r2][2].y : zA[r2][2].x);
                    float zo = DA[3][r2 * 2 + j] + (j ? zA[r2][3].y : zA[r2][3].x);
                    float cn = siga(zf) * c[ri][j] + siga(zi) * tanha(zg);
                    float hn = siga(zo) * tanha(cn);
                    if (upd) { c[ri][j] = cn; h[ri][j] = hn; }
                }
                __nv_bfloat16 b0 = __float2bfloat16(h[ri][0]);
                __nv_bfloat16 b1 = __float2bfloat16(h[ri][1]);
                uint32_t hw = (uint32_t)__bfloat16_as_ushort(b0)
                            | ((uint32_t)__bfloat16_as_ushort(b1) << 16);
                uint32_t lw = pack_bf16x2(h[ri][0] - __bfloat162float(b0),
                                          h[ri][1] - __bfloat162float(b1));
                const int word = rown[ri] * HROW + w * 4 + tg;
                sHhi[word] = hw; sHlo[word] = lw;
                if (MODE == 0 && upd) {
                    size_t o = ((size_t)offr[ri] + t) * HSZ + u0;
                    *(uint32_t*)&g_h0hi[o] = hw;
                    *(uint32_t*)&g_h0lo[o] = lw;
                }
            }
        }
        __syncthreads();
    }

    // final act_B(Lmax-1)
    {
        const int tb = Lmax - 1;
        #pragma unroll
        for (int r2 = 0; r2 < 2; r2++) {
            const int ri = 2 + r2;
            const bool upd = cv && (tb < lenr[ri]);
            #pragma unroll
            for (int j = 0; j < 2; j++) {
                float zi = DB[0][r2 * 2 + j] + (j ? zB[r2][0].y : zB[r2][0].x);
                float zf = DB[1][r2 * 2 + j] + (j ? zB[r2][1].y : zB[r2][1].x);
                float zg = DB[2][r2 * 2 + j] + (j ? zB[r2][2].y : zB[r2][2].x);
                float zo = DB[3][r2 * 2 + j] + (j ? zB[r2][3].y : zB[r2][3].x);
                float cn = siga(zf) * c[ri][j] + siga(zi) * tanha(zg);
                float hn = siga(zo) * tanha(cn);
                if (upd) { c[ri][j] = cn; h[ri][j] = hn; }
            }
            if (MODE == 0 && upd) {
                __nv_bfloat16 b0 = __float2bfloat16(h[ri][0]);
                __nv_bfloat16 b1 = __float2bfloat16(h[ri][1]);
                uint32_t hw = (uint32_t)__bfloat16_as_ushort(b0)
                            | ((uint32_t)__bfloat16_as_ushort(b1) << 16);
                uint32_t lw = pack_bf16x2(h[ri][0] - __bfloat162float(b0),
                                          h[ri][1] - __bfloat162float(b1));
                size_t o = ((size_t)offr[ri] + tb) * HSZ + u0;
                *(uint32_t*)&g_h0hi[o] = hw;
                *(uint32_t*)&g_h0lo[o] = lw;
            }
        }
    }

    if (MODE == 1) {
        __syncthreads();    // everyone past W reads before sHF overwrite
        #pragma unroll
        for (int ri = 0; ri < 4; ri++) {
            if (cv) {
                sHF[rown[ri] * HSZ + u0]     = h[ri][0];
                sHF[rown[ri] * HSZ + u0 + 1] = h[ri][1];
            }
        }
        __syncthreads();
        if (tid < 32) {
            float s = bfc[0];
            #pragma unroll 10
            for (int k = 0; k < HSZ; k++) s += sHF[tid * HSZ + k] * sWf[k];
            out[grow0 + tid] = s;
        }
    }
}

// ===========================================================================
// Kernel G: zpack = h0pack @ Wih1^T + bias1 (unchanged from R6)
// ===========================================================================
__global__ void __launch_bounds__(512, 1)
k_gemm_mma(const float* __restrict__ bih1, const float* __restrict__ bhh1)
{
    extern __shared__ char smc[];
    float*          sBias = (float*)smc;
    __nv_bfloat16*  sAhi  = (__nv_bfloat16*)(smc + 1600);
    __nv_bfloat16*  sAlo  = (__nv_bfloat16*)(smc + 32320);
    __nv_bfloat16*  sBhi  = (__nv_bfloat16*)(smc + 63040);
    __nv_bfloat16*  sBlo  = (__nv_bfloat16*)(smc + 116800);

    const int tid  = threadIdx.x;
    const int wid  = tid >> 5, lane = tid & 31;
    const int g    = lane >> 2, tg = lane & 3;
    const int wm   = (wid & 3) * 32;
    const int wn   = (wid >> 2) * 56;

    for (int i = tid; i < G4; i += 512) sBias[i] = bih1[i] + bhh1[i];
    for (int i = tid; i < 128 * 20; i += 512) {
        int r = i / 20, kk = 100 + i % 20;
        sAhi[r * LDA + kk] = __float2bfloat16(0.f);
        sAlo[r * LDA + kk] = __float2bfloat16(0.f);
    }
    for (int i = tid; i < 24 * LDB; i += 512) {
        int r = 200 + i / LDB, kk = i % LDB;
        sBhi[r * LDB + kk] = __float2bfloat16(0.f);
        sBlo[r * LDB + kk] = __float2bfloat16(0.f);
    }

    const uint32_t aHiB = smem_u32(sAhi) + ((lane & 15) * (LDA/2) + (lane >> 4) * 4) * 4;
    const uint32_t aLoB = smem_u32(sAlo) + ((lane & 15) * (LDA/2) + (lane >> 4) * 4) * 4;

    const int Mpack  = g_off_arr[BSZ];
    const int ntiles = (Mpack + 127) >> 7;
    const int nitems = ntiles * 2;
    int curHalf = -1;

    #pragma unroll 1
    for (int it = blockIdx.x; it < nitems; it += gridDim.x) {
        const int half  = (it >= ntiles) ? 1 : 0;
        const int mtile = it - half * ntiles;
        const size_t m0 = (size_t)mtile << 7;
        const int jo    = half * 200;

        __syncthreads();
        if (half != curHalf) {
            curHalf = half;
            #pragma unroll 1
            for (int i = tid; i < 200 * 14; i += 512) {
                int n = i / 14, kc = (i % 14) * 8;
                size_t go = (size_t)(jo + n) * KP + kc;
                *(uint4*)&sBhi[n * LDB + kc] = *(const uint4*)&g_bhi[go];
                *(uint4*)&sBlo[n * LDB + kc] = *(const uint4*)&g_blo[go];
            }
        }
        #pragma unroll 1
        for (int i = tid; i < 128 * 25; i += 512) {
            int r = i / 25, kc = (i % 25) * 4;
            size_t go = (m0 + r) * HSZ + kc;
            *(uint2*)&sAhi[r * LDA + kc] = *(const uint2*)&g_h0hi[go];
            *(uint2*)&sAlo[r * LDA + kc] = *(const uint2*)&g_h0lo[go];
        }
        __syncthreads();

        float D[2][7][4];
        #pragma unroll
        for (int mt = 0; mt < 2; mt++)
            #pragma unroll
            for (int nt = 0; nt < 7; nt++)
                #pragma unroll
                for (int q = 0; q < 4; q++) D[mt][nt][q] = 0.f;

        #pragma unroll
        for (int ks = 0; ks < 7; ks++) {
            uint32_t ahi[2][4], alo[2][4];
            #pragma unroll
            for (int mt = 0; mt < 2; mt++) {
                const uint32_t off = ((wm + mt * 16) * (LDA/2) + ks * 8) * 4;
                ldsm4(ahi[mt], aHiB + off);
                ldsm4(alo[mt], aLoB + off);
            }
            const int kb = ks * 16;
            #pragma unroll
            for (int nt = 0; nt < 7; nt++) {
                const int brow = (wn + nt * 8 + g) * LDB + kb + 2 * tg;
                uint32_t bh0 = *(const uint32_t*)&sBhi[brow];
                uint32_t bh1 = *(const uint32_t*)&sBhi[brow + 8];
                uint32_t bl0 = *(const uint32_t*)&sBlo[brow];
                uint32_t bl1 = *(const uint32_t*)&sBlo[brow + 8];
                #pragma unroll
                for (int mt = 0; mt < 2; mt++) {
                    mma_bf16(D[mt][nt], ahi[mt], bh0, bh1);
                    mma_bf16(D[mt][nt], alo[mt], bh0, bh1);
                    mma_bf16(D[mt][nt], ahi[mt], bl0, bl1);
                }
            }
        }

        #pragma unroll
        for (int mt = 0; mt < 2; mt++) {
            #pragma unroll
            for (int nt = 0; nt < 7; nt++) {
                int n_rel = wn + nt * 8 + 2 * tg;
                if (n_rel < 200) {
                    int ncol = jo + n_rel;
                    float b0v = sBias[ncol], b1v = sBias[ncol + 1];
                    size_t R = m0 + wm + mt * 16 + g;
                    if (R < (size_t)Mpack) {
                        float2 v = make_float2(D[mt][nt][0] + b0v, D[mt][nt][1] + b1v);
                        *(float2*)&g_zpack[R * G4 + ncol] = v;
                    }
                    if (R + 8 < (size_t)Mpack) {
                        float2 v = make_float2(D[mt][nt][2] + b0v, D[mt][nt][3] + b1v);
                        *(float2*)&g_zpack[(R + 8) * G4 + ncol] = v;
                    }
                }
            }
        }
    }
}

// ===========================================================================
// Launch
// ===========================================================================
extern "C" void kernel_launch(void* const* d_in, const int* in_sizes, int n_in,
                              void* d_out, int out_size)
{
    const float* x       = (const float*)d_in[0];
    const int*   lengths = (const int*)  d_in[1];
    const float* Wih0    = (const float*)d_in[2];
    const float* Whh0    = (const float*)d_in[3];
    const float* bih0    = (const float*)d_in[4];
    const float* bhh0    = (const float*)d_in[5];
    const float* Wih1    = (const float*)d_in[6];
    const float* Whh1    = (const float*)d_in[7];
    const float* bih1    = (const float*)d_in[8];
    const float* bhh1    = (const float*)d_in[9];
    const float* Wfc     = (const float*)d_in[10];
    const float* bfc     = (const float*)d_in[11];
    float* out = (float*)d_out;

    uint32_t *w2hi0, *w2lo0, *w2hi1, *w2lo1;
    cudaGetSymbolAddress((void**)&w2hi0, g_w2hi0);
    cudaGetSymbolAddress((void**)&w2lo0, g_w2lo0);
    cudaGetSymbolAddress((void**)&w2hi1, g_w2hi1);
    cudaGetSymbolAddress((void**)&w2lo1, g_w2lo1);

    const int smG = 1600 + 2 * 30720 + 2 * 53760;   // 170,560
    const int smR = 204544;

    cudaFuncSetAttribute(k_gemm_mma, cudaFuncAttributeMaxDynamicSharedMemorySize, smG);
    cudaFuncSetAttribute(k_rec<0>,   cudaFuncAttributeMaxDynamicSharedMemorySize, smR);
    cudaFuncSetAttribute(k_rec<1>,   cudaFuncAttributeMaxDynamicSharedMemorySize, smR);

    k_scan  <<<1, 512>>>(lengths);
    k_wsplit<<<(G4 * KP + 255) / 256, 256>>>(Wih1);
    k_wprep <<<(W2N + 255) / 256, 256>>>(Whh0, w2hi0, w2lo0);
    k_wprep <<<(W2N + 255) / 256, 256>>>(Whh1, w2hi1, w2lo1);
    k_zx0   <<<128, 512>>>(x, lengths, Wih0, bih0, bhh0);
    k_rec<0><<<128, RTH, smR>>>(lengths, nullptr, nullptr, nullptr);
    k_gemm_mma<<<148, 512, smG>>>(bih1, bhh1);
    k_rec<1><<<128, RTH, smR>>>(lengths, Wfc, bfc, out);
}

// round 9
// speedup vs baseline: 1.4156x; 1.4156x over previous
#include <cuda_runtime.h>
#include <cuda_fp16.h>
#include <cstdint>
#include <cstddef>

// Problem constants
#define BSZ 4096
#define TSZ 100
#define FSZ 13
#define HSZ 100
#define G4  400

// GEMM constants
#define KP   112
#define LDA  120
#define LDB  120

// Recurrent kernel constants
#define RW    13
#define RTH   (RW*32)
#define W2N   23296         // W fragment words (52 ntiles * 7 kt * 64)
#define HROW  68            // h row stride in words
#define HBUFW (32*HROW)     // 2176 words per buffer

// ---------------------------------------------------------------------------
// Scratch (device globals)
// ---------------------------------------------------------------------------
__device__ __half g_h0hi[(size_t)BSZ * TSZ * HSZ];
__device__ __half g_h0lo[(size_t)BSZ * TSZ * HSZ];
__device__ __half g_bh[G4 * KP];                  // W_ih1 fp16 (gemm layout)
__device__ float g_zpack [(size_t)BSZ * TSZ * G4];
__device__ float g_z0pack[(size_t)BSZ * TSZ * G4];
__device__ int   g_off_arr[BSZ + 1];
__device__ uint32_t g_w2h0[W2N];                  // Whh0 fp16 frag layout
__device__ uint32_t g_w2h1[W2N];                  // Whh1 fp16 frag layout

// ---------------------------------------------------------------------------
// Helpers
// ---------------------------------------------------------------------------
__device__ __forceinline__ float tanha(float x) {
    float y;
    asm("tanh.approx.f32 %0, %1;" : "=f"(y) : "f"(x));
    return y;
}
__device__ __forceinline__ float siga(float x) {
    return fmaf(0.5f, tanha(0.5f * x), 0.5f);
}
__device__ __forceinline__ void ffma2(unsigned long long &d,
                                      unsigned long long a,
                                      unsigned long long b) {
    asm("fma.rn.f32x2 %0, %1, %2, %0;" : "+l"(d) : "l"(a), "l"(b));
}
__device__ __forceinline__ unsigned long long pk(float lo, float hi) {
    unsigned long long r;
    asm("mov.b64 %0, {%1, %2};" : "=l"(r) : "f"(lo), "f"(hi));
    return r;
}
__device__ __forceinline__ float psum(unsigned long long a) {
    float lo = __uint_as_float((unsigned)(a & 0xffffffffull));
    float hi = __uint_as_float((unsigned)(a >> 32));
    return lo + hi;
}
__device__ __forceinline__ void mma_fp16(float* d, const uint32_t* a,
                                         uint32_t b0, uint32_t b1) {
    asm volatile(
        "mma.sync.aligned.m16n8k16.row.col.f32.f16.f16.f32 "
        "{%0,%1,%2,%3}, {%4,%5,%6,%7}, {%8,%9}, {%0,%1,%2,%3};"
        : "+f"(d[0]), "+f"(d[1]), "+f"(d[2]), "+f"(d[3])
        : "r"(a[0]), "r"(a[1]), "r"(a[2]), "r"(a[3]), "r"(b0), "r"(b1));
}
__device__ __forceinline__ void ldsm4(uint32_t* r, uint32_t addr) {
    asm volatile("ldmatrix.sync.aligned.m8n8.x4.shared.b16 {%0,%1,%2,%3}, [%4];"
        : "=r"(r[0]), "=r"(r[1]), "=r"(r[2]), "=r"(r[3]) : "r"(addr));
}
__device__ __forceinline__ uint32_t smem_u32(const void* p) {
    uint32_t a;
    asm("{ .reg .u64 t; cvta.to.shared.u64 t, %1; cvt.u32.u64 %0, t; }"
        : "=r"(a) : "l"(p));
    return a;
}
// pack two floats -> half2 word; also return the fp32 residuals
__device__ __forceinline__ void split_h2(float f0, float f1,
                                         uint32_t &hw, uint32_t &lw) {
    __half2 h2 = __float22half2_rn(make_float2(f0, f1));
    hw = *(uint32_t*)&h2;
    float2 back = __half22float2(h2);
    __half2 l2 = __float22half2_rn(make_float2(f0 - back.x, f1 - back.y));
    lw = *(uint32_t*)&l2;
}

// ===========================================================================
// Kernel S: exclusive prefix scan of lengths (1 CTA)
// ===========================================================================
__global__ void __launch_bounds__(512, 1) k_scan(const int* __restrict__ lengths)
{
    __shared__ int s[512];
    const int tid = threadIdx.x;
    const int base = tid * 8;
    int v[8]; int loc = 0;
    #pragma unroll
    for (int i = 0; i < 8; i++) { v[i] = lengths[base + i]; loc += v[i]; }
    s[tid] = loc;
    __syncthreads();
    for (int d = 1; d < 512; d <<= 1) {
        int t = (tid >= d) ? s[tid - d] : 0;
        __syncthreads();
        s[tid] += t;
        __syncthreads();
    }
    int run = s[tid] - loc;
    #pragma unroll
    for (int i = 0; i < 8; i++) { g_off_arr[base + i] = run; run += v[i]; }
    if (tid == 511) g_off_arr[BSZ] = s[511];
}

// ===========================================================================
// Kernel W1: W_ih1 -> fp16 (gemm layout, k-padded)
// ===========================================================================
__global__ void __launch_bounds__(256, 1) k_wsplit(const float* __restrict__ Wih1)
{
    int idx = blockIdx.x * 256 + threadIdx.x;
    if (idx < G4 * KP) {
        int n = idx / KP, k = idx % KP;
        float v = (k < HSZ) ? Wih1[n * HSZ + k] : 0.f;
        g_bh[idx] = __float2half(v);
    }
}

// ===========================================================================
// Kernel W2: Whh -> fp16 pair-packed fragment layout
// ===========================================================================
__global__ void __launch_bounds__(256, 1)
k_wprep(const float* __restrict__ W, uint32_t* __restrict__ dh)
{
    int j = blockIdx.x * 256 + threadIdx.x;
    if (j >= W2N) return;
    int sel = j & 1;
    int pp  = (j >> 1) & 31;
    int tg  = pp >> 3, g = pp & 7;
    int grp = j >> 6;
    int kt  = grp % 7, n = grp / 7;
    int row = n * 8 + g;
    int gate = row / 104, u = row % 104;
    int k    = kt * 16 + 2 * tg + 8 * sel;
    float f0 = (u < HSZ && k     < HSZ) ? W[(gate * HSZ + u) * HSZ + k]     : 0.f;
    float f1 = (u < HSZ && k + 1 < HSZ) ? W[(gate * HSZ + u) * HSZ + k + 1] : 0.f;
    __half2 h2 = __float22half2_rn(make_float2(f0, f1));
    dh[j] = *(uint32_t*)&h2;
}

// ===========================================================================
// Kernel Z0: g_z0pack = bias0 + x @ Wih0^T (packed rows, fp32)
// ===========================================================================
__global__ void __launch_bounds__(512, 1)
k_zx0(const float* __restrict__ x, const int* __restrict__ lengths,
      const float* __restrict__ Wih0,
      const float* __restrict__ bih0, const float* __restrict__ bhh0)
{
    __shared__ float sX[1400];
    __shared__ int sLen[32], sOff[32];
    const int tid = threadIdx.x;
    const int grow0 = blockIdx.x * 32;
    if (tid < 32) {
        sLen[tid] = lengths[grow0 + tid];
        sOff[tid] = g_off_arr[grow0 + tid];
    }
    const int u = tid;
    const bool act = (u < G4);
    unsigned long long wp[7];
    float b = 0.f;
    if (act) {
        float wr[14];
        #pragma unroll
        for (int k = 0; k < FSZ; k++) wr[k] = Wih0[u * FSZ + k];
        wr[13] = 0.f;
        #pragma unroll
        for (int i = 0; i < 7; i++) wp[i] = pk(wr[2*i], wr[2*i+1]);
        b = bih0[u] + bhh0[u];
    }
    __syncthreads();

    for (int r = 0; r < 32; r++) {
        const int len = sLen[r], off = sOff[r];
        __syncthreads();
        const float* xs = x + (size_t)(grow0 + r) * (TSZ * FSZ);
        for (int i = tid; i < 1400; i += 512) {
            int t = i / 14, k = i % 14;
            sX[i] = (k < FSZ) ? xs[t * FSZ + k] : 0.f;
        }
        __syncthreads();
        if (act) {
            for (int t = 0; t < len; t++) {
                unsigned long long acc = pk(b, 0.f);
                #pragma unroll
                for (int kp = 0; kp < 7; kp++)
                    ffma2(acc, wp[kp], *(const unsigned long long*)&sX[t*14 + 2*kp]);
                g_z0pack[(size_t)(off + t) * G4 + u] = psum(acc);
            }
        }
    }
}

// ===========================================================================
// Kernel R: fp16x2-split tensor-core LSTM layer (R6 structure, 1 barrier/step)
// ===========================================================================
template<int MODE>
__global__ void __launch_bounds__(RTH, 1)
k_rec(const int* __restrict__ lengths,
      const float* __restrict__ Wfc, const float* __restrict__ bfc,
      float* __restrict__ out)
{
    extern __shared__ char smc[];
    uint32_t* sW   = (uint32_t*)(smc);                 // 93184 B
    uint32_t* sHhi = (uint32_t*)(smc + 93184);         // 2 x 8704 B
    uint32_t* sHlo = (uint32_t*)(smc + 110592);        // 2 x 8704 B
    int*   sLen = (int*)(smc + 128000);
    int*   sOff = (int*)(smc + 128128);
    float* sWf  = (float*)(smc + 128256);
    float* sHF  = (float*)(smc);                       // fc reuse (after loop)

    const uint32_t* gwh = MODE ? g_w2h1 : g_w2h0;
    const float*    zsrc = MODE ? g_zpack : g_z0pack;

    const int tid = threadIdx.x;
    const int grow0 = blockIdx.x * 32;

    for (int i = tid; i < W2N; i += RTH) sW[i] = gwh[i];
    for (int i = tid; i < 2 * HBUFW; i += RTH) { sHhi[i] = 0u; sHlo[i] = 0u; }
    if (tid < 32) {
        sLen[tid] = lengths[grow0 + tid];
        sOff[tid] = g_off_arr[grow0 + tid];
    }
    if (MODE == 1 && tid < HSZ) sWf[tid] = Wfc[tid];
    __syncthreads();

    int Lmax = 0;
    #pragma unroll
    for (int r = 0; r < 32; r++) Lmax = max(Lmax, sLen[r]);

    const int w = tid >> 5, lane = tid & 31;
    const int g = lane >> 2, tg = lane & 3;
    const int u0 = w * 8 + 2 * tg;
    const bool cv = (u0 < HSZ);

    const uint32_t sb = smem_u32(smc);
    const uint32_t lmoff = ((lane & 15) * HROW + (lane >> 4) * 4) * 4;
    const uint32_t hHiB = sb + 93184 + lmoff;
    const uint32_t hLoB = sb + 110592 + lmoff;

    int rown[4], lenr[4], offr[4];
    #pragma unroll
    for (int ri = 0; ri < 4; ri++) {
        int mt = ri >> 1, rh = ri & 1;
        rown[ri] = mt * 16 + rh * 8 + g;
        lenr[ri] = sLen[rown[ri]];
        offr[ri] = sOff[rown[ri]];
    }
    float c[4][2] = {{0.f,0.f},{0.f,0.f},{0.f,0.f},{0.f,0.f}};
    float h[4][2] = {{0.f,0.f},{0.f,0.f},{0.f,0.f},{0.f,0.f}};

    int p = 0;
    #pragma unroll 1
    for (int t = 0; t < Lmax; t++) {
        // z(t) prefetch (consumed after the MMA block)
        float2 zn[4][4];
        #pragma unroll
        for (int ri = 0; ri < 4; ri++) {
            const bool lv = cv && (t < lenr[ri]);
            const size_t zb = (size_t)(offr[ri] + t) * G4;
            #pragma unroll
            for (int G = 0; G < 4; G++)
                zn[ri][G] = lv ? *(const float2*)&zsrc[zb + G * HSZ + u0]
                               : make_float2(0.f, 0.f);
        }

        float D[2][4][4];
        #pragma unroll
        for (int mt = 0; mt < 2; mt++)
            #pragma unroll
            for (int G = 0; G < 4; G++)
                #pragma unroll
                for (int q = 0; q < 4; q++) D[mt][G][q] = 0.f;

        const uint32_t hHi = hHiB + p * 8704;
        const uint32_t hLo = hLoB + p * 8704;
        #pragma unroll
        for (int kt = 0; kt < 7; kt++) {
            uint32_t ahi[2][4], alo[2][4];
            #pragma unroll
            for (int mt = 0; mt < 2; mt++) {
                const uint32_t off = (mt * 16 * HROW + kt * 8) * 4;
                ldsm4(ahi[mt], hHi + off);
                ldsm4(alo[mt], hLo + off);
            }
            #pragma unroll
            for (int G = 0; G < 4; G++) {
                const int b2 = (((G * 13 + w) * 7 + kt) * 32 + tg * 8 + g) * 2;
                uint2 bh = *(const uint2*)&sW[b2];
                #pragma unroll
                for (int mt = 0; mt < 2; mt++) {
                    mma_fp16(D[mt][G], ahi[mt], bh.x, bh.y);
                    mma_fp16(D[mt][G], alo[mt], bh.x, bh.y);
                }
            }
        }

        // activation + state update + stage h(t+1) into buffer 1-p
        uint32_t* Nh = sHhi + (1 - p) * HBUFW;
        uint32_t* Nl = sHlo + (1 - p) * HBUFW;
        #pragma unroll
        for (int ri = 0; ri < 4; ri++) {
            const int mt = ri >> 1, rh = ri & 1;
            const bool upd = cv && (t < lenr[ri]);
            #pragma unroll
            for (int j = 0; j < 2; j++) {
                float zi = D[mt][0][rh * 2 + j] + (j ? zn[ri][0].y : zn[ri][0].x);
                float zf = D[mt][1][rh * 2 + j] + (j ? zn[ri][1].y : zn[ri][1].x);
                float zg = D[mt][2][rh * 2 + j] + (j ? zn[ri][2].y : zn[ri][2].x);
                float zo = D[mt][3][rh * 2 + j] + (j ? zn[ri][3].y : zn[ri][3].x);
                float cn = siga(zf) * c[ri][j] + siga(zi) * tanha(zg);
                float hn = siga(zo) * tanha(cn);
                if (upd) { c[ri][j] = cn; h[ri][j] = hn; }
            }
            uint32_t hw, lw;
            split_h2(h[ri][0], h[ri][1], hw, lw);
            const int word = rown[ri] * HROW + w * 4 + tg;
            Nh[word] = hw; Nl[word] = lw;
            if (MODE == 0 && upd) {
                size_t o = ((size_t)offr[ri] + t) * HSZ + u0;
                *(uint32_t*)&g_h0hi[o] = hw;
                *(uint32_t*)&g_h0lo[o] = lw;
            }
        }
        __syncthreads();
        p ^= 1;
    }

    if (MODE == 1) {
        #pragma unroll
        for (int ri = 0; ri < 4; ri++) {
            if (cv) {
                sHF[rown[ri] * HSZ + u0]     = h[ri][0];
                sHF[rown[ri] * HSZ + u0 + 1] = h[ri][1];
            }
        }
        __syncthreads();
        if (tid < 32) {
            float s = bfc[0];
            #pragma unroll 10
            for (int k = 0; k < HSZ; k++) s += sHF[tid * HSZ + k] * sWf[k];
            out[grow0 + tid] = s;
        }
    }
}

// ===========================================================================
// Kernel G: zpack = h0pack @ Wih1^T + bias1 (fp16x2 split, 2-term)
// ===========================================================================
__global__ void __launch_bounds__(512, 1)
k_gemm_mma(const float* __restrict__ bih1, const float* __restrict__ bhh1)
{
    extern __shared__ char smc[];
    float*   sBias = (float*)smc;                      // 1600
    __half*  sAhi  = (__half*)(smc + 1600);            // 30720
    __half*  sAlo  = (__half*)(smc + 32320);           // 30720
    __half*  sBh   = (__half*)(smc + 63040);           // 53760

    const int tid  = threadIdx.x;
    const int wid  = tid >> 5, lane = tid & 31;
    const int g    = lane >> 2, tg = lane & 3;
    const int wm   = (wid & 3) * 32;
    const int wn   = (wid >> 2) * 56;

    for (int i = tid; i < G4; i += 512) sBias[i] = bih1[i] + bhh1[i];
    for (int i = tid; i < 128 * 20; i += 512) {
        int r = i / 20, kk = 100 + i % 20;
        sAhi[r * LDA + kk] = __float2half(0.f);
        sAlo[r * LDA + kk] = __float2half(0.f);
    }
    for (int i = tid; i < 24 * LDB; i += 512) {
        int r = 200 + i / LDB, kk = i % LDB;
        sBh[r * LDB + kk] = __float2half(0.f);
    }

    const uint32_t aHiB = smem_u32(sAhi) + ((lane & 15) * (LDA/2) + (lane >> 4) * 4) * 4;
    const uint32_t aLoB = smem_u32(sAlo) + ((lane & 15) * (LDA/2) + (lane >> 4) * 4) * 4;

    const int Mpack  = g_off_arr[BSZ];
    const int ntiles = (Mpack + 127) >> 7;
    const int nitems = ntiles * 2;
    int curHalf = -1;

    #pragma unroll 1
    for (int it = blockIdx.x; it < nitems; it += gridDim.x) {
        const int half  = (it >= ntiles) ? 1 : 0;
        const int mtile = it - half * ntiles;
        const size_t m0 = (size_t)mtile << 7;
        const int jo    = half * 200;

        __syncthreads();
        if (half != curHalf) {
            curHalf = half;
            #pragma unroll 1
            for (int i = tid; i < 200 * 14; i += 512) {
                int n = i / 14, kc = (i % 14) * 8;
                size_t go = (size_t)(jo + n) * KP + kc;
                *(uint4*)&sBh[n * LDB + kc] = *(const uint4*)&g_bh[go];
            }
        }
        #pragma unroll 1
        for (int i = tid; i < 128 * 25; i += 512) {
            int r = i / 25, kc = (i % 25) * 4;
            size_t go = (m0 + r) * HSZ + kc;
            *(uint2*)&sAhi[r * LDA + kc] = *(const uint2*)&g_h0hi[go];
            *(uint2*)&sAlo[r * LDA + kc] = *(const uint2*)&g_h0lo[go];
        }
        __syncthreads();

        float D[2][7][4];
        #pragma unroll
        for (int mt = 0; mt < 2; mt++)
            #pragma unroll
            for (int nt = 0; nt < 7; nt++)
                #pragma unroll
                for (int q = 0; q < 4; q++) D[mt][nt][q] = 0.f;

        #pragma unroll
        for (int ks = 0; ks < 7; ks++) {
            uint32_t ahi[2][4], alo[2][4];
            #pragma unroll
            for (int mt = 0; mt < 2; mt++) {
                const uint32_t off = ((wm + mt * 16) * (LDA/2) + ks * 8) * 4;
                ldsm4(ahi[mt], aHiB + off);
                ldsm4(alo[mt], aLoB + off);
            }
            const int kb = ks * 16;
            #pragma unroll
            for (int nt = 0; nt < 7; nt++) {
                const int brow = (wn + nt * 8 + g) * LDB + kb + 2 * tg;
                uint32_t b0 = *(const uint32_t*)&sBh[brow];
                uint32_t b1 = *(const uint32_t*)&sBh[brow + 8];
                #pragma unroll
                for (int mt = 0; mt < 2; mt++) {
                    mma_fp16(D[mt][nt], ahi[mt], b0, b1);
                    mma_fp16(D[mt][nt], alo[mt], b0, b1);
                }
            }
        }

        #pragma unroll
        for (int mt = 0; mt < 2; mt++) {
            #pragma unroll
            for (int nt = 0; nt < 7; nt++) {
                int n_rel = wn + nt * 8 + 2 * tg;
                if (n_rel < 200) {
                    int ncol = jo + n_rel;
                    float b0v = sBias[ncol], b1v = sBias[ncol + 1];
                    size_t R = m0 + wm + mt * 16 + g;
                    if (R < (size_t)Mpack) {
                        float2 v = make_float2(D[mt][nt][0] + b0v, D[mt][nt][1] + b1v);
                        *(float2*)&g_zpack[R * G4 + ncol] = v;
                    }
                    if (R + 8 < (size_t)Mpack) {
                        float2 v = make_float2(D[mt][nt][2] + b0v, D[mt][nt][3] + b1v);
                        *(float2*)&g_zpack[(R + 8) * G4 + ncol] = v;
                    }
                }
            }
        }
    }
}

// ===========================================================================
// Launch
// ===========================================================================
extern "C" void kernel_launch(void* const* d_in, const int* in_sizes, int n_in,
                              void* d_out, int out_size)
{
    const float* x       = (const float*)d_in[0];
    const int*   lengths = (const int*)  d_in[1];
    const float* Wih0    = (const float*)d_in[2];
    const float* Whh0    = (const float*)d_in[3];
    const float* bih0    = (const float*)d_in[4];
    const float* bhh0    = (const float*)d_in[5];
    const float* Wih1    = (const float*)d_in[6];
    const float* Whh1    = (const float*)d_in[7];
    const float* bih1    = (const float*)d_in[8];
    const float* bhh1    = (const float*)d_in[9];
    const float* Wfc     = (const float*)d_in[10];
    const float* bfc     = (const float*)d_in[11];
    float* out = (float*)d_out;

    uint32_t *w2h0, *w2h1;
    cudaGetSymbolAddress((void**)&w2h0, g_w2h0);
    cudaGetSymbolAddress((void**)&w2h1, g_w2h1);

    const int smG = 1600 + 2 * 30720 + 53760;   // 116,800
    const int smR = 128656;

    cudaFuncSetAttribute(k_gemm_mma, cudaFuncAttributeMaxDynamicSharedMemorySize, smG);
    cudaFuncSetAttribute(k_rec<0>,   cudaFuncAttributeMaxDynamicSharedMemorySize, smR);
    cudaFuncSetAttribute(k_rec<1>,   cudaFuncAttributeMaxDynamicSharedMemorySize, smR);

    k_scan  <<<1, 512>>>(lengths);
    k_wsplit<<<(G4 * KP + 255) / 256, 256>>>(Wih1);
    k_wprep <<<(W2N + 255) / 256, 256>>>(Whh0, w2h0);
    k_wprep <<<(W2N + 255) / 256, 256>>>(Whh1, w2h1);
    k_zx0   <<<128, 512>>>(x, lengths, Wih0, bih0, bhh0);
    k_rec<0><<<128, RTH, smR>>>(lengths, nullptr, nullptr, nullptr);
    k_gemm_mma<<<148, 512, smG>>>(bih1, bhh1);
    k_rec<1><<<128, RTH, smR>>>(lengths, Wfc, bfc, out);
}